// round 1
// baseline (speedup 1.0000x reference)
#include <cuda_runtime.h>
#include <math.h>

#define D_MODEL 1024
#define N_HEAD 16
#define HEAD_DIM 64
#define BATCH 2
#define SEQ 2048
#define M_ROWS (BATCH * SEQ)   // 4096

// ---------------- scratch (static device arrays; no allocation allowed) ----
__device__ float g_q[M_ROWS * D_MODEL];
__device__ float g_k[M_ROWS * D_MODEL];
__device__ float g_v[M_ROWS * D_MODEL];
__device__ float g_ctx[M_ROWS * D_MODEL];

// ============================================================================
// SGEMM: C[M,N] = A[M,K] @ B[K,N], all row-major fp32.
// 128x128 block tile, BK=16, 256 threads, 8x8 per thread.
// ============================================================================
#define GBM 128
#define GBN 128
#define GBK 16

__global__ __launch_bounds__(256, 2)
void sgemm_kernel(const float* __restrict__ A, const float* __restrict__ B,
                  float* __restrict__ C, int M, int N, int K)
{
    __shared__ float As[GBK * GBM];   // transposed: As[k*GBM + m]
    __shared__ float Bs[GBK * GBN];   // Bs[k*GBN + n]

    const int tid = threadIdx.x;
    const int ty = tid >> 4;          // 0..15
    const int tx = tid & 15;          // 0..15
    const int rowBase = blockIdx.y * GBM;
    const int colBase = blockIdx.x * GBN;

    float acc[8][8];
#pragma unroll
    for (int i = 0; i < 8; i++)
#pragma unroll
        for (int j = 0; j < 8; j++) acc[i][j] = 0.f;

    for (int k0 = 0; k0 < K; k0 += GBK) {
        // Load A tile (128 x 16), store transposed into As[k][m]
#pragma unroll
        for (int it = 0; it < 2; it++) {
            int f  = it * 256 + tid;          // 0..511 float4 slots
            int r  = f >> 2;                  // 0..127
            int c4 = (f & 3) * 4;             // 0,4,8,12
            float4 v = *(const float4*)&A[(size_t)(rowBase + r) * K + k0 + c4];
            As[(c4 + 0) * GBM + r] = v.x;
            As[(c4 + 1) * GBM + r] = v.y;
            As[(c4 + 2) * GBM + r] = v.z;
            As[(c4 + 3) * GBM + r] = v.w;
        }
        // Load B tile (16 x 128)
#pragma unroll
        for (int it = 0; it < 2; it++) {
            int f  = it * 256 + tid;          // 0..511
            int r  = f >> 5;                  // 0..15
            int c4 = (f & 31) * 4;            // 0..124
            *(float4*)&Bs[r * GBN + c4] =
                *(const float4*)&B[(size_t)(k0 + r) * N + colBase + c4];
        }
        __syncthreads();

#pragma unroll
        for (int kk = 0; kk < GBK; kk++) {
            float4 a0 = *(float4*)&As[kk * GBM + ty * 8];
            float4 a1 = *(float4*)&As[kk * GBM + ty * 8 + 4];
            float4 b0 = *(float4*)&Bs[kk * GBN + tx * 8];
            float4 b1 = *(float4*)&Bs[kk * GBN + tx * 8 + 4];
            float a[8] = {a0.x, a0.y, a0.z, a0.w, a1.x, a1.y, a1.z, a1.w};
            float b[8] = {b0.x, b0.y, b0.z, b0.w, b1.x, b1.y, b1.z, b1.w};
#pragma unroll
            for (int i = 0; i < 8; i++)
#pragma unroll
                for (int j = 0; j < 8; j++)
                    acc[i][j] += a[i] * b[j];
        }
        __syncthreads();
    }

#pragma unroll
    for (int i = 0; i < 8; i++) {
        size_t r = (size_t)(rowBase + ty * 8 + i) * N + colBase + tx * 8;
#pragma unroll
        for (int j = 0; j < 8; j += 4) {
            float4 v = make_float4(acc[i][j], acc[i][j + 1], acc[i][j + 2], acc[i][j + 3]);
            *(float4*)&C[r + j] = v;
        }
    }
}

// ============================================================================
// Causal flash attention, fp32, online softmax.
// Per block: one (b,h) pair and a 64-row Q tile. 256 threads (16x16), 4x4 micro.
// smem: Qt[d][r] (d-major, padded), Kt[d][c] (reused as Pt[c][r]), Vs[c][d].
// ============================================================================
#define ABM 64
#define ABN 64
#define LDT 68   // padded leading dim for transposed tiles (multiple of 4)

extern __shared__ float att_smem[];

__global__ __launch_bounds__(256)
void attn_kernel(const float* __restrict__ Q, const float* __restrict__ K,
                 const float* __restrict__ V, float* __restrict__ ctx)
{
    float* Qt = att_smem;            // [64 d][LDT r]
    float* Kt = Qt + 64 * LDT;       // [64 d][LDT c], reused as Pt[64 c][LDT r]
    float* Vs = Kt + 64 * LDT;       // [64 c][64 d]

    const int tid = threadIdx.x;
    const int ty = tid >> 4;         // 0..15 (q-row group)
    const int tx = tid & 15;         // 0..15 (col/dim group)
    const int bh = blockIdx.y;       // 0..B*H-1
    const int b  = bh / N_HEAD;
    const int h  = bh % N_HEAD;
    const int q0 = blockIdx.x * ABM;
    const int baseRow = b * SEQ;
    const int headCol = h * HEAD_DIM;
    const float scale = 0.125f;      // 1/sqrt(64)

    // Load Q tile transposed (scale folded into Q)
#pragma unroll
    for (int it = 0; it < 4; it++) {
        int f  = it * 256 + tid;     // 0..1023
        int r  = f >> 4;             // 0..63
        int c4 = (f & 15) * 4;       // 0..60
        float4 v = *(const float4*)&Q[(size_t)(baseRow + q0 + r) * D_MODEL + headCol + c4];
        Qt[(c4 + 0) * LDT + r] = v.x * scale;
        Qt[(c4 + 1) * LDT + r] = v.y * scale;
        Qt[(c4 + 2) * LDT + r] = v.z * scale;
        Qt[(c4 + 3) * LDT + r] = v.w * scale;
    }

    float m_i[4], l_i[4], o[4][4];
#pragma unroll
    for (int i = 0; i < 4; i++) {
        m_i[i] = -INFINITY;
        l_i[i] = 0.f;
#pragma unroll
        for (int j = 0; j < 4; j++) o[i][j] = 0.f;
    }
    __syncthreads();

    for (int k0 = 0; k0 <= q0; k0 += ABN) {
        // Load K tile transposed + V tile natural
#pragma unroll
        for (int it = 0; it < 4; it++) {
            int f  = it * 256 + tid;
            int r  = f >> 4;
            int c4 = (f & 15) * 4;
            float4 kv = *(const float4*)&K[(size_t)(baseRow + k0 + r) * D_MODEL + headCol + c4];
            Kt[(c4 + 0) * LDT + r] = kv.x;
            Kt[(c4 + 1) * LDT + r] = kv.y;
            Kt[(c4 + 2) * LDT + r] = kv.z;
            Kt[(c4 + 3) * LDT + r] = kv.w;
            *(float4*)&Vs[r * 64 + c4] =
                *(const float4*)&V[(size_t)(baseRow + k0 + r) * D_MODEL + headCol + c4];
        }
        __syncthreads();

        // Scores s[i][j] = sum_d Qt[d][ty*4+i] * Kt[d][tx*4+j]
        float s[4][4];
#pragma unroll
        for (int i = 0; i < 4; i++)
#pragma unroll
            for (int j = 0; j < 4; j++) s[i][j] = 0.f;

#pragma unroll 16
        for (int d = 0; d < 64; d++) {
            float4 qv = *(float4*)&Qt[d * LDT + ty * 4];
            float4 kv = *(float4*)&Kt[d * LDT + tx * 4];
            float qa[4] = {qv.x, qv.y, qv.z, qv.w};
            float ka[4] = {kv.x, kv.y, kv.z, kv.w};
#pragma unroll
            for (int i = 0; i < 4; i++)
#pragma unroll
                for (int j = 0; j < 4; j++)
                    s[i][j] += qa[i] * ka[j];
        }

        // Causal mask only on the diagonal tile
        if (k0 == q0) {
#pragma unroll
            for (int i = 0; i < 4; i++) {
                int qr = ty * 4 + i;
#pragma unroll
                for (int j = 0; j < 4; j++) {
                    int kc = tx * 4 + j;
                    if (kc > qr) s[i][j] = -INFINITY;
                }
            }
        }

        // Online softmax update; 16-thread row groups are contiguous lanes.
        float p[4][4];
#pragma unroll
        for (int i = 0; i < 4; i++) {
            float rm = fmaxf(fmaxf(s[i][0], s[i][1]), fmaxf(s[i][2], s[i][3]));
#pragma unroll
            for (int off = 1; off < 16; off <<= 1)
                rm = fmaxf(rm, __shfl_xor_sync(0xffffffffu, rm, off));
            float newm = fmaxf(m_i[i], rm);
            float corr = (m_i[i] == -INFINITY) ? 0.f : __expf(m_i[i] - newm);
            float rs = 0.f;
#pragma unroll
            for (int j = 0; j < 4; j++) {
                p[i][j] = __expf(s[i][j] - newm);
                rs += p[i][j];
            }
#pragma unroll
            for (int off = 1; off < 16; off <<= 1)
                rs += __shfl_xor_sync(0xffffffffu, rs, off);
            l_i[i] = l_i[i] * corr + rs;
            m_i[i] = newm;
#pragma unroll
            for (int j = 0; j < 4; j++) o[i][j] *= corr;
        }

        __syncthreads();  // all threads done reading Kt before it becomes Pt

        // Store P transposed: Pt[c][r]
#pragma unroll
        for (int i = 0; i < 4; i++)
#pragma unroll
            for (int j = 0; j < 4; j++)
                Kt[(tx * 4 + j) * LDT + (ty * 4 + i)] = p[i][j];
        __syncthreads();

        // o[i][j] += sum_c Pt[c][ty*4+i] * Vs[c][tx*4+j]
#pragma unroll 16
        for (int c = 0; c < 64; c++) {
            float4 pv = *(float4*)&Kt[c * LDT + ty * 4];
            float4 vv = *(float4*)&Vs[c * 64 + tx * 4];
            float pa[4] = {pv.x, pv.y, pv.z, pv.w};
            float va[4] = {vv.x, vv.y, vv.z, vv.w};
#pragma unroll
            for (int i = 0; i < 4; i++)
#pragma unroll
                for (int j = 0; j < 4; j++)
                    o[i][j] += pa[i] * va[j];
        }
        __syncthreads();  // before next tile overwrites Kt / Vs
    }

    // Epilogue: ctx[b, q, h*64 + d] = o / l
#pragma unroll
    for (int i = 0; i < 4; i++) {
        float inv = 1.f / l_i[i];
        float4 v = make_float4(o[i][0] * inv, o[i][1] * inv, o[i][2] * inv, o[i][3] * inv);
        *(float4*)&ctx[(size_t)(baseRow + q0 + ty * 4 + i) * D_MODEL + headCol + tx * 4] = v;
    }
}

// ============================================================================
// Launch
// ============================================================================
extern "C" void kernel_launch(void* const* d_in, const int* in_sizes, int n_in,
                              void* d_out, int out_size)
{
    const float* x  = (const float*)d_in[0];
    const float* Wq = (const float*)d_in[1];
    const float* Wk = (const float*)d_in[2];
    const float* Wv = (const float*)d_in[3];
    const float* Wo = (const float*)d_in[4];
    float* out = (float*)d_out;

    float *q, *k, *v, *ctx;
    cudaGetSymbolAddress((void**)&q,   g_q);
    cudaGetSymbolAddress((void**)&k,   g_k);
    cudaGetSymbolAddress((void**)&v,   g_v);
    cudaGetSymbolAddress((void**)&ctx, g_ctx);

    dim3 gemmGrid(D_MODEL / GBN, M_ROWS / GBM);  // (8, 32)
    sgemm_kernel<<<gemmGrid, 256>>>(x, Wq, q, M_ROWS, D_MODEL, D_MODEL);
    sgemm_kernel<<<gemmGrid, 256>>>(x, Wk, k, M_ROWS, D_MODEL, D_MODEL);
    sgemm_kernel<<<gemmGrid, 256>>>(x, Wv, v, M_ROWS, D_MODEL, D_MODEL);

    size_t attSmem = (size_t)(2 * 64 * LDT + 64 * 64) * sizeof(float);  // 51200 B
    cudaFuncSetAttribute(attn_kernel, cudaFuncAttributeMaxDynamicSharedMemorySize,
                         (int)attSmem);
    dim3 attGrid(SEQ / ABM, BATCH * N_HEAD);     // (32, 32)
    attn_kernel<<<attGrid, 256, attSmem>>>(q, k, v, ctx);

    sgemm_kernel<<<gemmGrid, 256>>>(ctx, Wo, out, M_ROWS, D_MODEL, D_MODEL);
}

// round 3
// speedup vs baseline: 2.0505x; 2.0505x over previous
#include <cuda_runtime.h>
#include <cuda_bf16.h>
#include <stdint.h>
#include <math.h>

#define D_MODEL 1024
#define N_HEAD 16
#define HEAD_DIM 64
#define BATCH 2
#define SEQ 2048
#define M_ROWS (BATCH * SEQ)   // 4096
#define KP 3072                // split K' = 3*1024

// ---------------- scratch (static device arrays; no allocation allowed) ----
__device__ float g_q[M_ROWS * D_MODEL];
__device__ float g_k[M_ROWS * D_MODEL];
__device__ float g_v[M_ROWS * D_MODEL];
__device__ float g_ctx[M_ROWS * D_MODEL];

__device__ __nv_bfloat16 g_x2[M_ROWS * KP];      // [Ah | Ah | Al] of input
__device__ __nv_bfloat16 g_ctx2[M_ROWS * KP];    // same for ctx
__device__ __nv_bfloat16 g_wq2[D_MODEL * KP];    // [Wh^T | Wl^T | Wh^T]
__device__ __nv_bfloat16 g_wk2[D_MODEL * KP];
__device__ __nv_bfloat16 g_wv2[D_MODEL * KP];
__device__ __nv_bfloat16 g_wo2[D_MODEL * KP];

// ============================================================================
// Split helpers
// ============================================================================
__device__ __forceinline__ void split_bf16(float x, __nv_bfloat16& h, __nv_bfloat16& l)
{
    h = __float2bfloat16(x);
    l = __float2bfloat16(x - __bfloat162float(h));
}

// Split input rows: X[M][1024] fp32 -> X2[M][3072] bf16 = [h | h | l]
__global__ void split_rows_kernel(const float* __restrict__ X,
                                  __nv_bfloat16* __restrict__ X2, int M)
{
    int idx = blockIdx.x * blockDim.x + threadIdx.x;   // over M*512 (2 elems each)
    if (idx >= M * 512) return;
    int r = idx >> 9;
    int c = (idx & 511) * 2;
    float2 v = *(const float2*)&X[(size_t)r * D_MODEL + c];
    __nv_bfloat16 h0, l0, h1, l1;
    split_bf16(v.x, h0, l0);
    split_bf16(v.y, h1, l1);
    __nv_bfloat162 hh; hh.x = h0; hh.y = h1;
    __nv_bfloat162 ll; ll.x = l0; ll.y = l1;
    size_t base = (size_t)r * KP + c;
    *(__nv_bfloat162*)&X2[base]             = hh;
    *(__nv_bfloat162*)&X2[base + D_MODEL]   = hh;
    *(__nv_bfloat162*)&X2[base + 2*D_MODEL] = ll;
}

// Split + transpose weights: W[K=1024][N=1024] fp32 -> B2t[N][3072] = [h | l | h]
// (pairing with A blocks: Ah*Bh, Ah*Bl, Al*Bh)
__global__ void split_wT_kernel(const float* __restrict__ W,
                                __nv_bfloat16* __restrict__ B2t)
{
    __shared__ float t[32][33];
    const int k0 = blockIdx.y * 32, n0 = blockIdx.x * 32;
    const int tx = threadIdx.x, ty = threadIdx.y;   // 32 x 8
#pragma unroll
    for (int i = 0; i < 4; i++)
        t[ty + i * 8][tx] = W[(size_t)(k0 + ty + i * 8) * D_MODEL + n0 + tx];
    __syncthreads();
#pragma unroll
    for (int i = 0; i < 4; i++) {
        int n = n0 + ty + i * 8;
        int k = k0 + tx;
        float v = t[tx][ty + i * 8];
        __nv_bfloat16 h, l;
        split_bf16(v, h, l);
        size_t base = (size_t)n * KP;
        B2t[base + k]              = h;
        B2t[base + D_MODEL + k]    = l;
        B2t[base + 2*D_MODEL + k]  = h;
    }
}

// ============================================================================
// bf16 tensor-core GEMM: C[M,N] = A2[M,KP] @ B2t[N,KP]^T  (fp32 accumulate)
// Block 128x128, BK=32, 8 warps (2x4), warp tile 64x32, mma.m16n8k16.
// ============================================================================
#define TBK 32
#define TLD 40   // padded smem leading dim (bf16 elems)

__device__ __forceinline__ void mma16816(float c[4],
    uint32_t a0, uint32_t a1, uint32_t a2, uint32_t a3, uint32_t b0, uint32_t b1)
{
    asm volatile(
        "mma.sync.aligned.m16n8k16.row.col.f32.bf16.bf16.f32 "
        "{%0,%1,%2,%3}, {%4,%5,%6,%7}, {%8,%9}, {%0,%1,%2,%3};\n"
        : "+f"(c[0]), "+f"(c[1]), "+f"(c[2]), "+f"(c[3])
        : "r"(a0), "r"(a1), "r"(a2), "r"(a3), "r"(b0), "r"(b1));
}

__global__ __launch_bounds__(256)
void gemm_bf16_kernel(const __nv_bfloat16* __restrict__ A,   // [M][KP]
                      const __nv_bfloat16* __restrict__ Bt,  // [N][KP]
                      float* __restrict__ C, int N)
{
    __shared__ __nv_bfloat16 As[128 * TLD];
    __shared__ __nv_bfloat16 Bs[128 * TLD];

    const int tid  = threadIdx.x;
    const int wid  = tid >> 5;
    const int lane = tid & 31;
    const int g    = lane >> 2;        // 0..7
    const int q4   = lane & 3;         // 0..3
    const int warp_m = wid >> 2;       // 0..1
    const int warp_n = wid & 3;        // 0..3
    const int rowBase = blockIdx.y * 128;
    const int colBase = blockIdx.x * 128;

    float acc[4][4][4];
#pragma unroll
    for (int im = 0; im < 4; im++)
#pragma unroll
        for (int in = 0; in < 4; in++)
#pragma unroll
            for (int e = 0; e < 4; e++) acc[im][in][e] = 0.f;

    // global tile load: 128x32 bf16 per operand; 512 uint4 slots, 2/thread
    uint4 pa[2], pb[2];
    const int lr0 = tid >> 2;
    const int lc  = (tid & 3) * 8;

    auto loadTile = [&](int k0) {
        pa[0] = *(const uint4*)&A [(size_t)(rowBase + lr0)      * KP + k0 + lc];
        pa[1] = *(const uint4*)&A [(size_t)(rowBase + lr0 + 64) * KP + k0 + lc];
        pb[0] = *(const uint4*)&Bt[(size_t)(colBase + lr0)      * KP + k0 + lc];
        pb[1] = *(const uint4*)&Bt[(size_t)(colBase + lr0 + 64) * KP + k0 + lc];
    };
    auto storeTile = [&]() {
        *(uint4*)&As[(lr0)      * TLD + lc] = pa[0];
        *(uint4*)&As[(lr0 + 64) * TLD + lc] = pa[1];
        *(uint4*)&Bs[(lr0)      * TLD + lc] = pb[0];
        *(uint4*)&Bs[(lr0 + 64) * TLD + lc] = pb[1];
    };

    loadTile(0);
    storeTile();
    __syncthreads();

    for (int k0 = 0; k0 < KP; k0 += TBK) {
        bool more = (k0 + TBK) < KP;
        if (more) loadTile(k0 + TBK);

#pragma unroll
        for (int ks = 0; ks < 2; ks++) {
            const int kk = ks * 16 + q4 * 2;
            uint32_t bfr[4][2];
#pragma unroll
            for (int in = 0; in < 4; in++) {
                int n = warp_n * 32 + in * 8 + g;
                bfr[in][0] = *(const uint32_t*)&Bs[n * TLD + kk];
                bfr[in][1] = *(const uint32_t*)&Bs[n * TLD + kk + 8];
            }
#pragma unroll
            for (int im = 0; im < 4; im++) {
                int r = warp_m * 64 + im * 16 + g;
                uint32_t a0 = *(const uint32_t*)&As[(r)     * TLD + kk];
                uint32_t a1 = *(const uint32_t*)&As[(r + 8) * TLD + kk];
                uint32_t a2 = *(const uint32_t*)&As[(r)     * TLD + kk + 8];
                uint32_t a3 = *(const uint32_t*)&As[(r + 8) * TLD + kk + 8];
#pragma unroll
                for (int in = 0; in < 4; in++)
                    mma16816(acc[im][in], a0, a1, a2, a3, bfr[in][0], bfr[in][1]);
            }
        }
        __syncthreads();
        if (more) {
            storeTile();
            __syncthreads();
        }
    }

    // epilogue: fp32 direct stores
#pragma unroll
    for (int im = 0; im < 4; im++) {
        int r0 = rowBase + warp_m * 64 + im * 16 + g;
#pragma unroll
        for (int in = 0; in < 4; in++) {
            int col = colBase + warp_n * 32 + in * 8 + q4 * 2;
            float2 v0 = make_float2(acc[im][in][0], acc[im][in][1]);
            float2 v1 = make_float2(acc[im][in][2], acc[im][in][3]);
            *(float2*)&C[(size_t)(r0)     * N + col] = v0;
            *(float2*)&C[(size_t)(r0 + 8) * N + col] = v1;
        }
    }
}

// ============================================================================
// Causal flash attention, fp32, online softmax (unchanged from R1 — correct).
// ============================================================================
#define ABM 64
#define ABN 64
#define LDT 68

extern __shared__ float att_smem[];

__global__ __launch_bounds__(256)
void attn_kernel(const float* __restrict__ Q, const float* __restrict__ K,
                 const float* __restrict__ V, float* __restrict__ ctx)
{
    float* Qt = att_smem;
    float* Kt = Qt + 64 * LDT;
    float* Vs = Kt + 64 * LDT;

    const int tid = threadIdx.x;
    const int ty = tid >> 4;
    const int tx = tid & 15;
    const int bh = blockIdx.y;
    const int b  = bh / N_HEAD;
    const int h  = bh % N_HEAD;
    const int q0 = blockIdx.x * ABM;
    const int baseRow = b * SEQ;
    const int headCol = h * HEAD_DIM;
    const float scale = 0.125f;

#pragma unroll
    for (int it = 0; it < 4; it++) {
        int f  = it * 256 + tid;
        int r  = f >> 4;
        int c4 = (f & 15) * 4;
        float4 v = *(const float4*)&Q[(size_t)(baseRow + q0 + r) * D_MODEL + headCol + c4];
        Qt[(c4 + 0) * LDT + r] = v.x * scale;
        Qt[(c4 + 1) * LDT + r] = v.y * scale;
        Qt[(c4 + 2) * LDT + r] = v.z * scale;
        Qt[(c4 + 3) * LDT + r] = v.w * scale;
    }

    float m_i[4], l_i[4], o[4][4];
#pragma unroll
    for (int i = 0; i < 4; i++) {
        m_i[i] = -INFINITY;
        l_i[i] = 0.f;
#pragma unroll
        for (int j = 0; j < 4; j++) o[i][j] = 0.f;
    }
    __syncthreads();

    for (int k0 = 0; k0 <= q0; k0 += ABN) {
#pragma unroll
        for (int it = 0; it < 4; it++) {
            int f  = it * 256 + tid;
            int r  = f >> 4;
            int c4 = (f & 15) * 4;
            float4 kv = *(const float4*)&K[(size_t)(baseRow + k0 + r) * D_MODEL + headCol + c4];
            Kt[(c4 + 0) * LDT + r] = kv.x;
            Kt[(c4 + 1) * LDT + r] = kv.y;
            Kt[(c4 + 2) * LDT + r] = kv.z;
            Kt[(c4 + 3) * LDT + r] = kv.w;
            *(float4*)&Vs[r * 64 + c4] =
                *(const float4*)&V[(size_t)(baseRow + k0 + r) * D_MODEL + headCol + c4];
        }
        __syncthreads();

        float s[4][4];
#pragma unroll
        for (int i = 0; i < 4; i++)
#pragma unroll
            for (int j = 0; j < 4; j++) s[i][j] = 0.f;

#pragma unroll 16
        for (int d = 0; d < 64; d++) {
            float4 qv = *(float4*)&Qt[d * LDT + ty * 4];
            float4 kv = *(float4*)&Kt[d * LDT + tx * 4];
            float qa[4] = {qv.x, qv.y, qv.z, qv.w};
            float ka[4] = {kv.x, kv.y, kv.z, kv.w};
#pragma unroll
            for (int i = 0; i < 4; i++)
#pragma unroll
                for (int j = 0; j < 4; j++)
                    s[i][j] += qa[i] * ka[j];
        }

        if (k0 == q0) {
#pragma unroll
            for (int i = 0; i < 4; i++) {
                int qr = ty * 4 + i;
#pragma unroll
                for (int j = 0; j < 4; j++) {
                    int kc = tx * 4 + j;
                    if (kc > qr) s[i][j] = -INFINITY;
                }
            }
        }

        float p[4][4];
#pragma unroll
        for (int i = 0; i < 4; i++) {
            float rm = fmaxf(fmaxf(s[i][0], s[i][1]), fmaxf(s[i][2], s[i][3]));
#pragma unroll
            for (int off = 1; off < 16; off <<= 1)
                rm = fmaxf(rm, __shfl_xor_sync(0xffffffffu, rm, off));
            float newm = fmaxf(m_i[i], rm);
            float corr = (m_i[i] == -INFINITY) ? 0.f : __expf(m_i[i] - newm);
            float rs = 0.f;
#pragma unroll
            for (int j = 0; j < 4; j++) {
                p[i][j] = __expf(s[i][j] - newm);
                rs += p[i][j];
            }
#pragma unroll
            for (int off = 1; off < 16; off <<= 1)
                rs += __shfl_xor_sync(0xffffffffu, rs, off);
            l_i[i] = l_i[i] * corr + rs;
            m_i[i] = newm;
#pragma unroll
            for (int j = 0; j < 4; j++) o[i][j] *= corr;
        }

        __syncthreads();

#pragma unroll
        for (int i = 0; i < 4; i++)
#pragma unroll
            for (int j = 0; j < 4; j++)
                Kt[(tx * 4 + j) * LDT + (ty * 4 + i)] = p[i][j];
        __syncthreads();

#pragma unroll 16
        for (int c = 0; c < 64; c++) {
            float4 pv = *(float4*)&Kt[c * LDT + ty * 4];
            float4 vv = *(float4*)&Vs[c * 64 + tx * 4];
            float pa[4] = {pv.x, pv.y, pv.z, pv.w};
            float va[4] = {vv.x, vv.y, vv.z, vv.w};
#pragma unroll
            for (int i = 0; i < 4; i++)
#pragma unroll
                for (int j = 0; j < 4; j++)
                    o[i][j] += pa[i] * va[j];
        }
        __syncthreads();
    }

#pragma unroll
    for (int i = 0; i < 4; i++) {
        float inv = 1.f / l_i[i];
        float4 v = make_float4(o[i][0] * inv, o[i][1] * inv, o[i][2] * inv, o[i][3] * inv);
        *(float4*)&ctx[(size_t)(baseRow + q0 + ty * 4 + i) * D_MODEL + headCol + tx * 4] = v;
    }
}

// ============================================================================
// Launch
// ============================================================================
extern "C" void kernel_launch(void* const* d_in, const int* in_sizes, int n_in,
                              void* d_out, int out_size)
{
    const float* x  = (const float*)d_in[0];
    const float* Wq = (const float*)d_in[1];
    const float* Wk = (const float*)d_in[2];
    const float* Wv = (const float*)d_in[3];
    const float* Wo = (const float*)d_in[4];
    float* out = (float*)d_out;

    float *q, *k, *v, *ctx;
    __nv_bfloat16 *x2, *ctx2, *wq2, *wk2, *wv2, *wo2;
    cudaGetSymbolAddress((void**)&q,    g_q);
    cudaGetSymbolAddress((void**)&k,    g_k);
    cudaGetSymbolAddress((void**)&v,    g_v);
    cudaGetSymbolAddress((void**)&ctx,  g_ctx);
    cudaGetSymbolAddress((void**)&x2,   g_x2);
    cudaGetSymbolAddress((void**)&ctx2, g_ctx2);
    cudaGetSymbolAddress((void**)&wq2,  g_wq2);
    cudaGetSymbolAddress((void**)&wk2,  g_wk2);
    cudaGetSymbolAddress((void**)&wv2,  g_wv2);
    cudaGetSymbolAddress((void**)&wo2,  g_wo2);

    // 1. split/convert inputs
    split_rows_kernel<<<(M_ROWS * 512 + 255) / 256, 256>>>(x, x2, M_ROWS);
    dim3 wtGrid(32, 32), wtBlock(32, 8);
    split_wT_kernel<<<wtGrid, wtBlock>>>(Wq, wq2);
    split_wT_kernel<<<wtGrid, wtBlock>>>(Wk, wk2);
    split_wT_kernel<<<wtGrid, wtBlock>>>(Wv, wv2);
    split_wT_kernel<<<wtGrid, wtBlock>>>(Wo, wo2);

    // 2. Q/K/V projections (tensor core)
    dim3 gemmGrid(D_MODEL / 128, M_ROWS / 128);   // (8, 32)
    gemm_bf16_kernel<<<gemmGrid, 256>>>(x2, wq2, q, D_MODEL);
    gemm_bf16_kernel<<<gemmGrid, 256>>>(x2, wk2, k, D_MODEL);
    gemm_bf16_kernel<<<gemmGrid, 256>>>(x2, wv2, v, D_MODEL);

    // 3. attention (fp32)
    size_t attSmem = (size_t)(2 * 64 * LDT + 64 * 64) * sizeof(float);
    cudaFuncSetAttribute(attn_kernel, cudaFuncAttributeMaxDynamicSharedMemorySize,
                         (int)attSmem);
    dim3 attGrid(SEQ / ABM, BATCH * N_HEAD);
    attn_kernel<<<attGrid, 256, attSmem>>>(q, k, v, ctx);

    // 4. output projection
    split_rows_kernel<<<(M_ROWS * 512 + 255) / 256, 256>>>(ctx, ctx2, M_ROWS);
    gemm_bf16_kernel<<<gemmGrid, 256>>>(ctx2, wo2, out, D_MODEL);
}

// round 4
// speedup vs baseline: 2.8906x; 1.4097x over previous
#include <cuda_runtime.h>
#include <cuda_bf16.h>
#include <stdint.h>
#include <math.h>

#define D_MODEL 1024
#define N_HEAD 16
#define HEAD_DIM 64
#define BATCH 2
#define SEQ 2048
#define M_ROWS (BATCH * SEQ)   // 4096
#define KP 3072                // split K' = 3*1024 for projections
#define AKP 192                // split K' = 3*64 for attention

// ---------------- scratch (static device arrays; no allocation allowed) ----
__device__ float g_q[M_ROWS * D_MODEL];
__device__ float g_k[M_ROWS * D_MODEL];
__device__ float g_v[M_ROWS * D_MODEL];
__device__ float g_ctx[M_ROWS * D_MODEL];

__device__ __nv_bfloat16 g_x2[M_ROWS * KP];      // [Ah | Ah | Al] of input
__device__ __nv_bfloat16 g_ctx2[M_ROWS * KP];
__device__ __nv_bfloat16 g_wq2[D_MODEL * KP];    // [Wh^T | Wl^T | Wh^T]
__device__ __nv_bfloat16 g_wk2[D_MODEL * KP];
__device__ __nv_bfloat16 g_wv2[D_MODEL * KP];
__device__ __nv_bfloat16 g_wo2[D_MODEL * KP];

// attention operands (per (b,h) head-major)
__device__ __nv_bfloat16 g_Q2[32 * SEQ * AKP];           // [bh][s][qh|qh|ql] (scale folded)
__device__ __nv_bfloat16 g_K2[32 * SEQ * AKP];           // [bh][s][kh|kl|kh]
__device__ __nv_bfloat16 g_Vt2[32 * HEAD_DIM * 3 * SEQ]; // [bh][dh][tile t: vh|vl|vh]

// ============================================================================
// helpers
// ============================================================================
__device__ __forceinline__ void split_bf16(float x, __nv_bfloat16& h, __nv_bfloat16& l)
{
    h = __float2bfloat16(x);
    l = __float2bfloat16(x - __bfloat162float(h));
}

__device__ __forceinline__ uint32_t packbf(float a, float b)
{
    __nv_bfloat162 t = __floats2bfloat162_rn(a, b);
    return *reinterpret_cast<uint32_t*>(&t);
}

__device__ __forceinline__ void mma16816(float c[4],
    uint32_t a0, uint32_t a1, uint32_t a2, uint32_t a3, uint32_t b0, uint32_t b1)
{
    asm volatile(
        "mma.sync.aligned.m16n8k16.row.col.f32.bf16.bf16.f32 "
        "{%0,%1,%2,%3}, {%4,%5,%6,%7}, {%8,%9}, {%0,%1,%2,%3};\n"
        : "+f"(c[0]), "+f"(c[1]), "+f"(c[2]), "+f"(c[3])
        : "r"(a0), "r"(a1), "r"(a2), "r"(a3), "r"(b0), "r"(b1));
}

__device__ __forceinline__ void cpa16(void* sdst, const void* gsrc)
{
    uint32_t sa = (uint32_t)__cvta_generic_to_shared(sdst);
    asm volatile("cp.async.cg.shared.global [%0], [%1], 16;\n" :: "r"(sa), "l"(gsrc));
}
__device__ __forceinline__ void cpa_commit() { asm volatile("cp.async.commit_group;\n"); }
template <int N>
__device__ __forceinline__ void cpa_wait() { asm volatile("cp.async.wait_group %0;\n" :: "n"(N)); }

// ============================================================================
// Split input rows: X[M][1024] fp32 -> X2[M][3072] bf16 = [h | h | l]
// ============================================================================
__global__ void split_rows_kernel(const float* __restrict__ X,
                                  __nv_bfloat16* __restrict__ X2, int M)
{
    int idx = blockIdx.x * blockDim.x + threadIdx.x;
    if (idx >= M * 512) return;
    int r = idx >> 9;
    int c = (idx & 511) * 2;
    float2 v = *(const float2*)&X[(size_t)r * D_MODEL + c];
    __nv_bfloat16 h0, l0, h1, l1;
    split_bf16(v.x, h0, l0);
    split_bf16(v.y, h1, l1);
    __nv_bfloat162 hh; hh.x = h0; hh.y = h1;
    __nv_bfloat162 ll; ll.x = l0; ll.y = l1;
    size_t base = (size_t)r * KP + c;
    *(__nv_bfloat162*)&X2[base]             = hh;
    *(__nv_bfloat162*)&X2[base + D_MODEL]   = hh;
    *(__nv_bfloat162*)&X2[base + 2*D_MODEL] = ll;
}

// Split + transpose weights: W[K][N] fp32 -> B2t[N][3072] = [h | l | h]
__global__ void split_wT_kernel(const float* __restrict__ W,
                                __nv_bfloat16* __restrict__ B2t)
{
    __shared__ float t[32][33];
    const int k0 = blockIdx.y * 32, n0 = blockIdx.x * 32;
    const int tx = threadIdx.x, ty = threadIdx.y;
#pragma unroll
    for (int i = 0; i < 4; i++)
        t[ty + i * 8][tx] = W[(size_t)(k0 + ty + i * 8) * D_MODEL + n0 + tx];
    __syncthreads();
#pragma unroll
    for (int i = 0; i < 4; i++) {
        int n = n0 + ty + i * 8;
        int k = k0 + tx;
        float v = t[tx][ty + i * 8];
        __nv_bfloat16 h, l;
        split_bf16(v, h, l);
        size_t base = (size_t)n * KP;
        B2t[base + k]              = h;
        B2t[base + D_MODEL + k]    = l;
        B2t[base + 2*D_MODEL + k]  = h;
    }
}

// ============================================================================
// Q/K attention-operand split: g_q,g_k fp32 [m][h*64+d] -> Q2/K2 [bh][s][192]
// ============================================================================
__global__ void qk2_split_kernel(const float* __restrict__ Qf,
                                 const float* __restrict__ Kf,
                                 __nv_bfloat16* __restrict__ Q2,
                                 __nv_bfloat16* __restrict__ K2)
{
    int idx = blockIdx.x * blockDim.x + threadIdx.x;
    if (idx >= M_ROWS * 512) return;
    int r  = idx >> 9;
    int c2 = (idx & 511) * 2;
    int h  = c2 >> 6;
    int d  = c2 & 63;
    int b  = r / SEQ, s = r % SEQ;
    int bh = b * N_HEAD + h;
    size_t base = ((size_t)bh * SEQ + s) * AKP;

    float2 qv = *(const float2*)&Qf[(size_t)r * D_MODEL + c2];
    qv.x *= 0.125f; qv.y *= 0.125f;
    __nv_bfloat16 qh0, ql0, qh1, ql1;
    split_bf16(qv.x, qh0, ql0);
    split_bf16(qv.y, qh1, ql1);
    __nv_bfloat162 qh; qh.x = qh0; qh.y = qh1;
    __nv_bfloat162 ql; ql.x = ql0; ql.y = ql1;
    *(__nv_bfloat162*)&Q2[base + d]       = qh;
    *(__nv_bfloat162*)&Q2[base + 64 + d]  = qh;
    *(__nv_bfloat162*)&Q2[base + 128 + d] = ql;

    float2 kv = *(const float2*)&Kf[(size_t)r * D_MODEL + c2];
    __nv_bfloat16 kh0, kl0, kh1, kl1;
    split_bf16(kv.x, kh0, kl0);
    split_bf16(kv.y, kh1, kl1);
    __nv_bfloat162 kh; kh.x = kh0; kh.y = kh1;
    __nv_bfloat162 kl; kl.x = kl0; kl.y = kl1;
    *(__nv_bfloat162*)&K2[base + d]       = kh;
    *(__nv_bfloat162*)&K2[base + 64 + d]  = kl;
    *(__nv_bfloat162*)&K2[base + 128 + d] = kh;
}

// ============================================================================
// V transpose+split: g_v fp32 -> Vt2[bh][dh][t*192 + {vh(64)|vl(64)|vh(64)}]
// block = one (bh, kv-tile t); 256 threads
// ============================================================================
__global__ void vt2_split_kernel(const float* __restrict__ Vf,
                                 __nv_bfloat16* __restrict__ Vt2)
{
    __shared__ float tile[64][65];
    const int t  = blockIdx.x;
    const int bh = blockIdx.y;
    const int b  = bh >> 4, h = bh & 15;
    const int tid = threadIdx.x;

#pragma unroll
    for (int i = 0; i < 16; i++) {
        int e = i * 256 + tid;
        int s = e >> 6, d = e & 63;
        tile[s][d] = Vf[((size_t)(b * SEQ + t * 64 + s)) * D_MODEL + h * 64 + d];
    }
    __syncthreads();
#pragma unroll
    for (int i = 0; i < 16; i++) {
        int e  = i * 256 + tid;
        int dh = e >> 6, kv = e & 63;
        float v = tile[kv][dh];
        __nv_bfloat16 vh, vl;
        split_bf16(v, vh, vl);
        size_t base = ((size_t)bh * 64 + dh) * (3 * SEQ) + (size_t)t * AKP;
        Vt2[base + kv]        = vh;
        Vt2[base + 64 + kv]   = vl;
        Vt2[base + 128 + kv]  = vh;
    }
}

// ============================================================================
// bf16 tensor-core GEMM (projections) — same as R3
// ============================================================================
#define TBK 32
#define TLD 40

__global__ __launch_bounds__(256)
void gemm_bf16_kernel(const __nv_bfloat16* __restrict__ A,
                      const __nv_bfloat16* __restrict__ Bt,
                      float* __restrict__ C, int N)
{
    __shared__ __nv_bfloat16 As[128 * TLD];
    __shared__ __nv_bfloat16 Bs[128 * TLD];

    const int tid  = threadIdx.x;
    const int wid  = tid >> 5;
    const int lane = tid & 31;
    const int g    = lane >> 2;
    const int q4   = lane & 3;
    const int warp_m = wid >> 2;
    const int warp_n = wid & 3;
    const int rowBase = blockIdx.y * 128;
    const int colBase = blockIdx.x * 128;

    float acc[4][4][4];
#pragma unroll
    for (int im = 0; im < 4; im++)
#pragma unroll
        for (int in = 0; in < 4; in++)
#pragma unroll
            for (int e = 0; e < 4; e++) acc[im][in][e] = 0.f;

    uint4 pa[2], pb[2];
    const int lr0 = tid >> 2;
    const int lc  = (tid & 3) * 8;

    auto loadTile = [&](int k0) {
        pa[0] = *(const uint4*)&A [(size_t)(rowBase + lr0)      * KP + k0 + lc];
        pa[1] = *(const uint4*)&A [(size_t)(rowBase + lr0 + 64) * KP + k0 + lc];
        pb[0] = *(const uint4*)&Bt[(size_t)(colBase + lr0)      * KP + k0 + lc];
        pb[1] = *(const uint4*)&Bt[(size_t)(colBase + lr0 + 64) * KP + k0 + lc];
    };
    auto storeTile = [&]() {
        *(uint4*)&As[(lr0)      * TLD + lc] = pa[0];
        *(uint4*)&As[(lr0 + 64) * TLD + lc] = pa[1];
        *(uint4*)&Bs[(lr0)      * TLD + lc] = pb[0];
        *(uint4*)&Bs[(lr0 + 64) * TLD + lc] = pb[1];
    };

    loadTile(0);
    storeTile();
    __syncthreads();

    for (int k0 = 0; k0 < KP; k0 += TBK) {
        bool more = (k0 + TBK) < KP;
        if (more) loadTile(k0 + TBK);

#pragma unroll
        for (int ks = 0; ks < 2; ks++) {
            const int kk = ks * 16 + q4 * 2;
            uint32_t bfr[4][2];
#pragma unroll
            for (int in = 0; in < 4; in++) {
                int n = warp_n * 32 + in * 8 + g;
                bfr[in][0] = *(const uint32_t*)&Bs[n * TLD + kk];
                bfr[in][1] = *(const uint32_t*)&Bs[n * TLD + kk + 8];
            }
#pragma unroll
            for (int im = 0; im < 4; im++) {
                int r = warp_m * 64 + im * 16 + g;
                uint32_t a0 = *(const uint32_t*)&As[(r)     * TLD + kk];
                uint32_t a1 = *(const uint32_t*)&As[(r + 8) * TLD + kk];
                uint32_t a2 = *(const uint32_t*)&As[(r)     * TLD + kk + 8];
                uint32_t a3 = *(const uint32_t*)&As[(r + 8) * TLD + kk + 8];
#pragma unroll
                for (int in = 0; in < 4; in++)
                    mma16816(acc[im][in], a0, a1, a2, a3, bfr[in][0], bfr[in][1]);
            }
        }
        __syncthreads();
        if (more) {
            storeTile();
            __syncthreads();
        }
    }

#pragma unroll
    for (int im = 0; im < 4; im++) {
        int r0 = rowBase + warp_m * 64 + im * 16 + g;
#pragma unroll
        for (int in = 0; in < 4; in++) {
            int col = colBase + warp_n * 32 + in * 8 + q4 * 2;
            float2 v0 = make_float2(acc[im][in][0], acc[im][in][1]);
            float2 v1 = make_float2(acc[im][in][2], acc[im][in][3]);
            *(float2*)&C[(size_t)(r0)     * N + col] = v0;
            *(float2*)&C[(size_t)(r0 + 8) * N + col] = v1;
        }
    }
}

// ============================================================================
// Tensor-core causal flash attention.
// CTA = (b,h) x 128 q rows; 8 warps, each 16 q rows x full 64 kv / 64 dh.
// K'=192 split contraction for both QK^T and PV.
// ============================================================================
#define KLD 200                      // smem leading dim (bf16 elems) per 192-row
#define ATT_SMEM (2 * (64 * KLD + 64 * KLD) * 2)  // 102400 bytes

extern __shared__ __nv_bfloat16 attn_sm[];

__global__ __launch_bounds__(256)
void attn_tc_kernel(const __nv_bfloat16* __restrict__ Q2,
                    const __nv_bfloat16* __restrict__ K2,
                    const __nv_bfloat16* __restrict__ Vt2,
                    float* __restrict__ ctx)
{
    const int tid  = threadIdx.x;
    const int w    = tid >> 5;
    const int lane = tid & 31;
    const int g    = lane >> 2;
    const int q4   = lane & 3;
    const int bh   = blockIdx.y;
    const int b    = bh >> 4, h = bh & 15;
    const int q0   = (gridDim.x - 1 - blockIdx.x) * 128;   // heavy CTAs first
    const int nt   = q0 / 64 + 2;
    const int qw   = q0 + w * 16;                           // warp's first q row

    // smem: double-buffered K tile [64][KLD] + V tile [64][KLD]
    __nv_bfloat16* Kb[2] = { attn_sm,               attn_sm + 25600 };
    __nv_bfloat16* Vb[2] = { attn_sm + 12800,       attn_sm + 25600 + 12800 };

    // ---- load Q fragments (held in registers all kernel) ----
    uint32_t qa[12][4];
    {
        const __nv_bfloat16* Qbase = Q2 + ((size_t)bh * SEQ + qw) * AKP;
#pragma unroll
        for (int ks = 0; ks < 12; ks++) {
            int kk = ks * 16 + 2 * q4;
            qa[ks][0] = *(const uint32_t*)&Qbase[(g)     * AKP + kk];
            qa[ks][1] = *(const uint32_t*)&Qbase[(g + 8) * AKP + kk];
            qa[ks][2] = *(const uint32_t*)&Qbase[(g)     * AKP + kk + 8];
            qa[ks][3] = *(const uint32_t*)&Qbase[(g + 8) * AKP + kk + 8];
        }
    }

    const __nv_bfloat16* Kg = K2  + (size_t)bh * SEQ * AKP;
    const __nv_bfloat16* Vg = Vt2 + (size_t)bh * HEAD_DIM * (3 * SEQ);

    // tile loader: 64x192 bf16 each for K and V (3072 x 16B chunks total)
    auto issueTile = [&](int t, int bi) {
        const __nv_bfloat16* ksrc = Kg + (size_t)t * 64 * AKP;
        const __nv_bfloat16* vsrc = Vg + (size_t)t * AKP;
        __nv_bfloat16* kd = Kb[bi];
        __nv_bfloat16* vd = Vb[bi];
#pragma unroll
        for (int i = 0; i < 6; i++) {
            int c   = i * 256 + tid;       // 0..1535
            int row = c / 24;
            int col = (c % 24) * 8;
            cpa16(&kd[row * KLD + col], &ksrc[row * AKP + col]);
            cpa16(&vd[row * KLD + col], &vsrc[(size_t)row * (3 * SEQ) + col]);
        }
        cpa_commit();
    };

    float O[8][4];
#pragma unroll
    for (int j = 0; j < 8; j++)
#pragma unroll
        for (int e = 0; e < 4; e++) O[j][e] = 0.f;
    float m0 = -INFINITY, m1 = -INFINITY, l0 = 0.f, l1 = 0.f;

    issueTile(0, 0);
    if (nt > 1) issueTile(1, 1);

    for (int t = 0; t < nt; t++) {
        if (t + 1 < nt) cpa_wait<1>(); else cpa_wait<0>();
        __syncthreads();

        const __nv_bfloat16* Ks = Kb[t & 1];
        const __nv_bfloat16* Vs = Vb[t & 1];
        const int k0 = t * 64;

        // ---- QK^T ----
        float S_[8][4];
#pragma unroll
        for (int j = 0; j < 8; j++)
#pragma unroll
            for (int e = 0; e < 4; e++) S_[j][e] = 0.f;

#pragma unroll
        for (int ks = 0; ks < 12; ks++) {
            const int kk = ks * 16 + 2 * q4;
            uint32_t a0 = qa[ks][0], a1 = qa[ks][1], a2 = qa[ks][2], a3 = qa[ks][3];
#pragma unroll
            for (int j = 0; j < 8; j++) {
                uint32_t b0 = *(const uint32_t*)&Ks[(j * 8 + g) * KLD + kk];
                uint32_t b1 = *(const uint32_t*)&Ks[(j * 8 + g) * KLD + kk + 8];
                mma16816(S_[j], a0, a1, a2, a3, b0, b1);
            }
        }

        // ---- causal mask (only when the tile straddles the diagonal) ----
        if (k0 + 63 > qw) {
            const int r0 = qw + g, r1 = r0 + 8;
#pragma unroll
            for (int j = 0; j < 8; j++) {
                int c0 = k0 + j * 8 + 2 * q4;
                if (c0     > r0) S_[j][0] = -INFINITY;
                if (c0 + 1 > r0) S_[j][1] = -INFINITY;
                if (c0     > r1) S_[j][2] = -INFINITY;
                if (c0 + 1 > r1) S_[j][3] = -INFINITY;
            }
        }

        // ---- online softmax ----
        float rmax0 = -INFINITY, rmax1 = -INFINITY;
#pragma unroll
        for (int j = 0; j < 8; j++) {
            rmax0 = fmaxf(rmax0, fmaxf(S_[j][0], S_[j][1]));
            rmax1 = fmaxf(rmax1, fmaxf(S_[j][2], S_[j][3]));
        }
        rmax0 = fmaxf(rmax0, __shfl_xor_sync(0xffffffffu, rmax0, 1));
        rmax0 = fmaxf(rmax0, __shfl_xor_sync(0xffffffffu, rmax0, 2));
        rmax1 = fmaxf(rmax1, __shfl_xor_sync(0xffffffffu, rmax1, 1));
        rmax1 = fmaxf(rmax1, __shfl_xor_sync(0xffffffffu, rmax1, 2));

        float nm0 = fmaxf(m0, rmax0), nm1 = fmaxf(m1, rmax1);
        float corr0 = __expf(m0 - nm0), corr1 = __expf(m1 - nm1);
        m0 = nm0; m1 = nm1;

        uint32_t ph[8][2], pl[8][2];
        float sum0 = 0.f, sum1 = 0.f;
#pragma unroll
        for (int j = 0; j < 8; j++) {
            float p00 = __expf(S_[j][0] - nm0);
            float p01 = __expf(S_[j][1] - nm0);
            float p10 = __expf(S_[j][2] - nm1);
            float p11 = __expf(S_[j][3] - nm1);
            sum0 += p00 + p01;
            sum1 += p10 + p11;
            uint32_t h0 = packbf(p00, p01);
            uint32_t h1 = packbf(p10, p11);
            ph[j][0] = h0; ph[j][1] = h1;
            __nv_bfloat162 hv0 = *reinterpret_cast<__nv_bfloat162*>(&h0);
            __nv_bfloat162 hv1 = *reinterpret_cast<__nv_bfloat162*>(&h1);
            pl[j][0] = packbf(p00 - __bfloat162float(hv0.x), p01 - __bfloat162float(hv0.y));
            pl[j][1] = packbf(p10 - __bfloat162float(hv1.x), p11 - __bfloat162float(hv1.y));
        }
        sum0 += __shfl_xor_sync(0xffffffffu, sum0, 1);
        sum0 += __shfl_xor_sync(0xffffffffu, sum0, 2);
        sum1 += __shfl_xor_sync(0xffffffffu, sum1, 1);
        sum1 += __shfl_xor_sync(0xffffffffu, sum1, 2);
        l0 = l0 * corr0 + sum0;
        l1 = l1 * corr1 + sum1;

#pragma unroll
        for (int j = 0; j < 8; j++) {
            O[j][0] *= corr0; O[j][1] *= corr0;
            O[j][2] *= corr1; O[j][3] *= corr1;
        }

        // ---- PV: phases vh(ph), vl(ph), vh(pl) ----
#pragma unroll
        for (int phase = 0; phase < 3; phase++) {
#pragma unroll
            for (int ksp = 0; ksp < 4; ksp++) {
                const int kk = phase * 64 + ksp * 16 + 2 * q4;
                uint32_t a0, a1, a2, a3;
                if (phase < 2) {
                    a0 = ph[2*ksp][0]; a1 = ph[2*ksp][1];
                    a2 = ph[2*ksp+1][0]; a3 = ph[2*ksp+1][1];
                } else {
                    a0 = pl[2*ksp][0]; a1 = pl[2*ksp][1];
                    a2 = pl[2*ksp+1][0]; a3 = pl[2*ksp+1][1];
                }
#pragma unroll
                for (int jn = 0; jn < 8; jn++) {
                    uint32_t b0 = *(const uint32_t*)&Vs[(jn * 8 + g) * KLD + kk];
                    uint32_t b1 = *(const uint32_t*)&Vs[(jn * 8 + g) * KLD + kk + 8];
                    mma16816(O[jn], a0, a1, a2, a3, b0, b1);
                }
            }
        }

        __syncthreads();
        if (t + 2 < nt) issueTile(t + 2, t & 1);
    }

    // ---- epilogue ----
    const float inv0 = 1.f / l0, inv1 = 1.f / l1;
    const int r0 = qw + g, r1 = r0 + 8;
    const int colBase = h * HEAD_DIM + 2 * q4;
#pragma unroll
    for (int jn = 0; jn < 8; jn++) {
        int col = colBase + jn * 8;
        *(float2*)&ctx[((size_t)(b * SEQ) + r0) * D_MODEL + col] =
            make_float2(O[jn][0] * inv0, O[jn][1] * inv0);
        *(float2*)&ctx[((size_t)(b * SEQ) + r1) * D_MODEL + col] =
            make_float2(O[jn][2] * inv1, O[jn][3] * inv1);
    }
}

// ============================================================================
// Launch
// ============================================================================
extern "C" void kernel_launch(void* const* d_in, const int* in_sizes, int n_in,
                              void* d_out, int out_size)
{
    const float* x  = (const float*)d_in[0];
    const float* Wq = (const float*)d_in[1];
    const float* Wk = (const float*)d_in[2];
    const float* Wv = (const float*)d_in[3];
    const float* Wo = (const float*)d_in[4];
    float* out = (float*)d_out;

    float *q, *k, *v, *ctx;
    __nv_bfloat16 *x2, *ctx2, *wq2, *wk2, *wv2, *wo2, *Q2, *K2, *Vt2;
    cudaGetSymbolAddress((void**)&q,    g_q);
    cudaGetSymbolAddress((void**)&k,    g_k);
    cudaGetSymbolAddress((void**)&v,    g_v);
    cudaGetSymbolAddress((void**)&ctx,  g_ctx);
    cudaGetSymbolAddress((void**)&x2,   g_x2);
    cudaGetSymbolAddress((void**)&ctx2, g_ctx2);
    cudaGetSymbolAddress((void**)&wq2,  g_wq2);
    cudaGetSymbolAddress((void**)&wk2,  g_wk2);
    cudaGetSymbolAddress((void**)&wv2,  g_wv2);
    cudaGetSymbolAddress((void**)&wo2,  g_wo2);
    cudaGetSymbolAddress((void**)&Q2,   g_Q2);
    cudaGetSymbolAddress((void**)&K2,   g_K2);
    cudaGetSymbolAddress((void**)&Vt2,  g_Vt2);

    // 1. split/convert inputs + weights
    split_rows_kernel<<<(M_ROWS * 512 + 255) / 256, 256>>>(x, x2, M_ROWS);
    dim3 wtGrid(32, 32), wtBlock(32, 8);
    split_wT_kernel<<<wtGrid, wtBlock>>>(Wq, wq2);
    split_wT_kernel<<<wtGrid, wtBlock>>>(Wk, wk2);
    split_wT_kernel<<<wtGrid, wtBlock>>>(Wv, wv2);
    split_wT_kernel<<<wtGrid, wtBlock>>>(Wo, wo2);

    // 2. Q/K/V projections
    dim3 gemmGrid(D_MODEL / 128, M_ROWS / 128);
    gemm_bf16_kernel<<<gemmGrid, 256>>>(x2, wq2, q, D_MODEL);
    gemm_bf16_kernel<<<gemmGrid, 256>>>(x2, wk2, k, D_MODEL);
    gemm_bf16_kernel<<<gemmGrid, 256>>>(x2, wv2, v, D_MODEL);

    // 3. attention operand prep
    qk2_split_kernel<<<(M_ROWS * 512 + 255) / 256, 256>>>(q, k, Q2, K2);
    vt2_split_kernel<<<dim3(SEQ / 64, 32), 256>>>(v, Vt2);

    // 4. tensor-core flash attention
    cudaFuncSetAttribute(attn_tc_kernel, cudaFuncAttributeMaxDynamicSharedMemorySize,
                         ATT_SMEM);
    attn_tc_kernel<<<dim3(SEQ / 128, 32), 256, ATT_SMEM>>>(Q2, K2, Vt2, ctx);

    // 5. output projection
    split_rows_kernel<<<(M_ROWS * 512 + 255) / 256, 256>>>(ctx, ctx2, M_ROWS);
    gemm_bf16_kernel<<<gemmGrid, 256>>>(ctx2, wo2, out, D_MODEL);
}

// round 6
// speedup vs baseline: 3.2714x; 1.1317x over previous
#include <cuda_runtime.h>
#include <cuda_bf16.h>
#include <stdint.h>
#include <math.h>

#define D_MODEL 1024
#define N_HEAD 16
#define HEAD_DIM 64
#define BATCH 2
#define SEQ 2048
#define M_ROWS (BATCH * SEQ)   // 4096
#define KP 3072                // split K' = 3*1024 for projections
#define AKP 192                // split K' = 3*64 for attention scores
#define AVP 128                // V split width (vh|vl)

// ---------------- scratch ----------------
__device__ float g_q[M_ROWS * D_MODEL];
__device__ float g_k[M_ROWS * D_MODEL];
__device__ float g_v[M_ROWS * D_MODEL];

__device__ __nv_bfloat16 g_x2[M_ROWS * KP];      // [Ah | Ah | Al]
__device__ __nv_bfloat16 g_ctx2[M_ROWS * KP];    // written by attention epilogue
__device__ __nv_bfloat16 g_wq2[D_MODEL * KP];    // [Wh^T | Wl^T | Wh^T]
__device__ __nv_bfloat16 g_wk2[D_MODEL * KP];
__device__ __nv_bfloat16 g_wv2[D_MODEL * KP];
__device__ __nv_bfloat16 g_wo2[D_MODEL * KP];

__device__ __nv_bfloat16 g_Q2[32 * SEQ * AKP];           // [bh][s][qh|qh|ql] (scale*log2e folded)
__device__ __nv_bfloat16 g_K2[32 * SEQ * AKP];           // [bh][s][kh|kl|kh]
__device__ __nv_bfloat16 g_Vt2[32 * HEAD_DIM * 2 * SEQ]; // [bh][dh][t: vh(64)|vl(64)]

// ============================================================================
// helpers
// ============================================================================
__device__ __forceinline__ void split_bf16(float x, __nv_bfloat16& h, __nv_bfloat16& l)
{
    h = __float2bfloat16(x);
    l = __float2bfloat16(x - __bfloat162float(h));
}

__device__ __forceinline__ uint32_t packbf(float a, float b)
{
    __nv_bfloat162 t = __floats2bfloat162_rn(a, b);
    return *reinterpret_cast<uint32_t*>(&t);
}

__device__ __forceinline__ float ex2f(float x)
{
    float y;
    asm("ex2.approx.ftz.f32 %0, %1;" : "=f"(y) : "f"(x));
    return y;
}

__device__ __forceinline__ void mma16816(float c[4],
    uint32_t a0, uint32_t a1, uint32_t a2, uint32_t a3, uint32_t b0, uint32_t b1)
{
    asm volatile(
        "mma.sync.aligned.m16n8k16.row.col.f32.bf16.bf16.f32 "
        "{%0,%1,%2,%3}, {%4,%5,%6,%7}, {%8,%9}, {%0,%1,%2,%3};\n"
        : "+f"(c[0]), "+f"(c[1]), "+f"(c[2]), "+f"(c[3])
        : "r"(a0), "r"(a1), "r"(a2), "r"(a3), "r"(b0), "r"(b1));
}

__device__ __forceinline__ void ldsm4(uint32_t& r0, uint32_t& r1, uint32_t& r2, uint32_t& r3,
                                      const void* p)
{
    uint32_t a = (uint32_t)__cvta_generic_to_shared(p);
    asm volatile("ldmatrix.sync.aligned.m8n8.x4.shared.b16 {%0,%1,%2,%3}, [%4];\n"
                 : "=r"(r0), "=r"(r1), "=r"(r2), "=r"(r3) : "r"(a));
}

__device__ __forceinline__ void cpa16(void* sdst, const void* gsrc)
{
    uint32_t sa = (uint32_t)__cvta_generic_to_shared(sdst);
    asm volatile("cp.async.cg.shared.global [%0], [%1], 16;\n" :: "r"(sa), "l"(gsrc));
}
__device__ __forceinline__ void cpa_commit() { asm volatile("cp.async.commit_group;\n"); }
template <int N>
__device__ __forceinline__ void cpa_wait() { asm volatile("cp.async.wait_group %0;\n" :: "n"(N)); }

// ============================================================================
// Split input rows: X[M][1024] fp32 -> X2[M][3072] bf16 = [h | h | l]
// ============================================================================
__global__ void split_rows_kernel(const float* __restrict__ X,
                                  __nv_bfloat16* __restrict__ X2, int M)
{
    int idx = blockIdx.x * blockDim.x + threadIdx.x;
    if (idx >= M * 512) return;
    int r = idx >> 9;
    int c = (idx & 511) * 2;
    float2 v = *(const float2*)&X[(size_t)r * D_MODEL + c];
    __nv_bfloat16 h0, l0, h1, l1;
    split_bf16(v.x, h0, l0);
    split_bf16(v.y, h1, l1);
    __nv_bfloat162 hh; hh.x = h0; hh.y = h1;
    __nv_bfloat162 ll; ll.x = l0; ll.y = l1;
    size_t base = (size_t)r * KP + c;
    *(__nv_bfloat162*)&X2[base]             = hh;
    *(__nv_bfloat162*)&X2[base + D_MODEL]   = hh;
    *(__nv_bfloat162*)&X2[base + 2*D_MODEL] = ll;
}

// Split + transpose weights: W[K][N] fp32 -> B2t[N][3072] = [h | l | h]
__global__ void split_wT_kernel(const float* __restrict__ W,
                                __nv_bfloat16* __restrict__ B2t)
{
    __shared__ float t[32][33];
    const int k0 = blockIdx.y * 32, n0 = blockIdx.x * 32;
    const int tx = threadIdx.x, ty = threadIdx.y;
#pragma unroll
    for (int i = 0; i < 4; i++)
        t[ty + i * 8][tx] = W[(size_t)(k0 + ty + i * 8) * D_MODEL + n0 + tx];
    __syncthreads();
#pragma unroll
    for (int i = 0; i < 4; i++) {
        int n = n0 + ty + i * 8;
        int k = k0 + tx;
        float v = t[tx][ty + i * 8];
        __nv_bfloat16 h, l;
        split_bf16(v, h, l);
        size_t base = (size_t)n * KP;
        B2t[base + k]              = h;
        B2t[base + D_MODEL + k]    = l;
        B2t[base + 2*D_MODEL + k]  = h;
    }
}

// ============================================================================
// Q/K attention split. Q gets scale*log2(e) folded (exp2 domain).
// ============================================================================
__global__ void qk2_split_kernel(const float* __restrict__ Qf,
                                 const float* __restrict__ Kf,
                                 __nv_bfloat16* __restrict__ Q2,
                                 __nv_bfloat16* __restrict__ K2)
{
    const float QSCALE = 0.125f * 1.44269504088896f;
    int idx = blockIdx.x * blockDim.x + threadIdx.x;
    if (idx >= M_ROWS * 512) return;
    int r  = idx >> 9;
    int c2 = (idx & 511) * 2;
    int h  = c2 >> 6;
    int d  = c2 & 63;
    int b  = r / SEQ, s = r % SEQ;
    int bh = b * N_HEAD + h;
    size_t base = ((size_t)bh * SEQ + s) * AKP;

    float2 qv = *(const float2*)&Qf[(size_t)r * D_MODEL + c2];
    qv.x *= QSCALE; qv.y *= QSCALE;
    __nv_bfloat16 qh0, ql0, qh1, ql1;
    split_bf16(qv.x, qh0, ql0);
    split_bf16(qv.y, qh1, ql1);
    __nv_bfloat162 qh; qh.x = qh0; qh.y = qh1;
    __nv_bfloat162 ql; ql.x = ql0; ql.y = ql1;
    *(__nv_bfloat162*)&Q2[base + d]       = qh;
    *(__nv_bfloat162*)&Q2[base + 64 + d]  = qh;
    *(__nv_bfloat162*)&Q2[base + 128 + d] = ql;

    float2 kv = *(const float2*)&Kf[(size_t)r * D_MODEL + c2];
    __nv_bfloat16 kh0, kl0, kh1, kl1;
    split_bf16(kv.x, kh0, kl0);
    split_bf16(kv.y, kh1, kl1);
    __nv_bfloat162 kh; kh.x = kh0; kh.y = kh1;
    __nv_bfloat162 kl; kl.x = kl0; kl.y = kl1;
    *(__nv_bfloat162*)&K2[base + d]       = kh;
    *(__nv_bfloat162*)&K2[base + 64 + d]  = kl;
    *(__nv_bfloat162*)&K2[base + 128 + d] = kh;
}

// ============================================================================
// V transpose+split: fp32 -> Vt2[bh][dh][t*128 + {vh(64)|vl(64)}]
// ============================================================================
__global__ void vt2_split_kernel(const float* __restrict__ Vf,
                                 __nv_bfloat16* __restrict__ Vt2)
{
    __shared__ float tile[64][65];
    const int t  = blockIdx.x;
    const int bh = blockIdx.y;
    const int b  = bh >> 4, h = bh & 15;
    const int tid = threadIdx.x;

#pragma unroll
    for (int i = 0; i < 16; i++) {
        int e = i * 256 + tid;
        int s = e >> 6, d = e & 63;
        tile[s][d] = Vf[((size_t)(b * SEQ + t * 64 + s)) * D_MODEL + h * 64 + d];
    }
    __syncthreads();
#pragma unroll
    for (int i = 0; i < 16; i++) {
        int e  = i * 256 + tid;
        int dh = e >> 6, kv = e & 63;
        float v = tile[kv][dh];
        __nv_bfloat16 vh, vl;
        split_bf16(v, vh, vl);
        size_t base = ((size_t)bh * 64 + dh) * (2 * SEQ) + (size_t)t * AVP;
        Vt2[base + kv]       = vh;
        Vt2[base + 64 + kv]  = vl;
    }
}

// ============================================================================
// bf16 tensor-core GEMM (projections)
// ============================================================================
#define TBK 32
#define TLD 40

__global__ __launch_bounds__(256)
void gemm_bf16_kernel(const __nv_bfloat16* __restrict__ A,
                      const __nv_bfloat16* __restrict__ Bt,
                      float* __restrict__ C, int N)
{
    __shared__ __nv_bfloat16 As[128 * TLD];
    __shared__ __nv_bfloat16 Bs[128 * TLD];

    const int tid  = threadIdx.x;
    const int wid  = tid >> 5;
    const int lane = tid & 31;
    const int g    = lane >> 2;
    const int q4   = lane & 3;
    const int warp_m = wid >> 2;
    const int warp_n = wid & 3;
    const int rowBase = blockIdx.y * 128;
    const int colBase = blockIdx.x * 128;

    float acc[4][4][4];
#pragma unroll
    for (int im = 0; im < 4; im++)
#pragma unroll
        for (int in = 0; in < 4; in++)
#pragma unroll
            for (int e = 0; e < 4; e++) acc[im][in][e] = 0.f;

    uint4 pa[2], pb[2];
    const int lr0 = tid >> 2;
    const int lc  = (tid & 3) * 8;

    auto loadTile = [&](int k0) {
        pa[0] = *(const uint4*)&A [(size_t)(rowBase + lr0)      * KP + k0 + lc];
        pa[1] = *(const uint4*)&A [(size_t)(rowBase + lr0 + 64) * KP + k0 + lc];
        pb[0] = *(const uint4*)&Bt[(size_t)(colBase + lr0)      * KP + k0 + lc];
        pb[1] = *(const uint4*)&Bt[(size_t)(colBase + lr0 + 64) * KP + k0 + lc];
    };
    auto storeTile = [&]() {
        *(uint4*)&As[(lr0)      * TLD + lc] = pa[0];
        *(uint4*)&As[(lr0 + 64) * TLD + lc] = pa[1];
        *(uint4*)&Bs[(lr0)      * TLD + lc] = pb[0];
        *(uint4*)&Bs[(lr0 + 64) * TLD + lc] = pb[1];
    };

    loadTile(0);
    storeTile();
    __syncthreads();

    for (int k0 = 0; k0 < KP; k0 += TBK) {
        bool more = (k0 + TBK) < KP;
        if (more) loadTile(k0 + TBK);

#pragma unroll
        for (int ks = 0; ks < 2; ks++) {
            const int kk = ks * 16 + q4 * 2;
            uint32_t bfr[4][2];
#pragma unroll
            for (int in = 0; in < 4; in++) {
                int n = warp_n * 32 + in * 8 + g;
                bfr[in][0] = *(const uint32_t*)&Bs[n * TLD + kk];
                bfr[in][1] = *(const uint32_t*)&Bs[n * TLD + kk + 8];
            }
#pragma unroll
            for (int im = 0; im < 4; im++) {
                int r = warp_m * 64 + im * 16 + g;
                uint32_t a0 = *(const uint32_t*)&As[(r)     * TLD + kk];
                uint32_t a1 = *(const uint32_t*)&As[(r + 8) * TLD + kk];
                uint32_t a2 = *(const uint32_t*)&As[(r)     * TLD + kk + 8];
                uint32_t a3 = *(const uint32_t*)&As[(r + 8) * TLD + kk + 8];
#pragma unroll
                for (int in = 0; in < 4; in++)
                    mma16816(acc[im][in], a0, a1, a2, a3, bfr[in][0], bfr[in][1]);
            }
        }
        __syncthreads();
        if (more) {
            storeTile();
            __syncthreads();
        }
    }

#pragma unroll
    for (int im = 0; im < 4; im++) {
        int r0 = rowBase + warp_m * 64 + im * 16 + g;
#pragma unroll
        for (int in = 0; in < 4; in++) {
            int col = colBase + warp_n * 32 + in * 8 + q4 * 2;
            float2 v0 = make_float2(acc[im][in][0], acc[im][in][1]);
            float2 v1 = make_float2(acc[im][in][2], acc[im][in][3]);
            *(float2*)&C[(size_t)(r0)     * N + col] = v0;
            *(float2*)&C[(size_t)(r0 + 8) * N + col] = v1;
        }
    }
}

// ============================================================================
// Tensor-core causal flash attention (LDSM fragments, 3-term PV w/ vh reuse).
// CTA = (b,h) x 128 q rows; 8 warps x 16 q rows.
// ============================================================================
#define KLD 200                         // K tile leading dim (elems)
#define VLD 136                         // V tile leading dim (elems)
#define KT_E (64 * KLD)                 // 12800 elems
#define VT_E (64 * VLD)                 // 8704 elems
#define BUF_E (KT_E + VT_E)             // 21504 elems
#define ATT_SMEM (2 * BUF_E * 2)        // 86016 bytes

extern __shared__ __nv_bfloat16 attn_sm[];

__global__ __launch_bounds__(256)
void attn_tc_kernel(const __nv_bfloat16* __restrict__ Q2,
                    const __nv_bfloat16* __restrict__ K2,
                    const __nv_bfloat16* __restrict__ Vt2,
                    __nv_bfloat16* __restrict__ ctx2)
{
    const int tid  = threadIdx.x;
    const int w    = tid >> 5;
    const int lane = tid & 31;
    const int g    = lane >> 2;
    const int q4   = lane & 3;
    const int bh   = blockIdx.y;
    const int b    = bh >> 4, h = bh & 15;
    const int q0   = (gridDim.x - 1 - blockIdx.x) * 128;   // heavy CTAs first
    const int nt   = q0 / 64 + 2;
    const int qw   = q0 + w * 16;

    // per-lane LDSM base offsets
    const int rowN  = lane & 7;
    const int ksel  = (lane >> 3) & 1;
    const int jsel  = lane >> 4;
    const int kOffE = (jsel * 8 + rowN) * KLD + ksel * 8;
    const int vOffE = (jsel * 8 + rowN) * VLD + ksel * 8;

    // ---- Q fragments in registers ----
    uint32_t qa[12][4];
    {
        const __nv_bfloat16* Qbase = Q2 + ((size_t)bh * SEQ + qw) * AKP;
#pragma unroll
        for (int ks = 0; ks < 12; ks++) {
            int kk = ks * 16 + 2 * q4;
            qa[ks][0] = *(const uint32_t*)&Qbase[(g)     * AKP + kk];
            qa[ks][1] = *(const uint32_t*)&Qbase[(g + 8) * AKP + kk];
            qa[ks][2] = *(const uint32_t*)&Qbase[(g)     * AKP + kk + 8];
            qa[ks][3] = *(const uint32_t*)&Qbase[(g + 8) * AKP + kk + 8];
        }
    }

    const __nv_bfloat16* Kg = K2  + (size_t)bh * SEQ * AKP;
    const __nv_bfloat16* Vg = Vt2 + (size_t)bh * HEAD_DIM * (2 * SEQ);

    auto issueTile = [&](int t, int bi) {
        const __nv_bfloat16* ksrc = Kg + (size_t)t * 64 * AKP;
        const __nv_bfloat16* vsrc = Vg + (size_t)t * AVP;
        __nv_bfloat16* kd = attn_sm + bi * BUF_E;
        __nv_bfloat16* vd = kd + KT_E;
#pragma unroll
        for (int i = 0; i < 6; i++) {           // K: 64 rows x 24 chunks
            int c   = i * 256 + tid;
            int row = c / 24;
            int col = (c % 24) * 8;
            cpa16(&kd[row * KLD + col], &ksrc[row * AKP + col]);
        }
#pragma unroll
        for (int i = 0; i < 4; i++) {           // V: 64 rows x 16 chunks
            int c   = i * 256 + tid;
            int row = c >> 4;
            int col = (c & 15) * 8;
            cpa16(&vd[row * VLD + col], &vsrc[(size_t)row * (2 * SEQ) + col]);
        }
        cpa_commit();
    };

    float O[8][4];
#pragma unroll
    for (int j = 0; j < 8; j++)
#pragma unroll
        for (int e = 0; e < 4; e++) O[j][e] = 0.f;
    float m0 = -INFINITY, m1 = -INFINITY, l0 = 0.f, l1 = 0.f;

    issueTile(0, 0);
    issueTile(1, 1);

    for (int t = 0; t < nt; t++) {
        if (t + 1 < nt) cpa_wait<1>(); else cpa_wait<0>();
        __syncthreads();

        const int k0 = t * 64;
        if (k0 <= qw + 15) {                     // skip fully-masked warp tiles
            const __nv_bfloat16* Ks = attn_sm + (t & 1) * BUF_E;
            const __nv_bfloat16* Vs = Ks + KT_E;

            // ---- QK^T via LDSM + mma ----
            float S_[8][4];
#pragma unroll
            for (int j = 0; j < 8; j++)
#pragma unroll
                for (int e = 0; e < 4; e++) S_[j][e] = 0.f;

#pragma unroll
            for (int ks = 0; ks < 12; ks++) {
                uint32_t a0 = qa[ks][0], a1 = qa[ks][1], a2 = qa[ks][2], a3 = qa[ks][3];
#pragma unroll
                for (int jj = 0; jj < 4; jj++) {
                    uint32_t b0, b1, b2, b3;
                    ldsm4(b0, b1, b2, b3, Ks + kOffE + jj * 16 * KLD + ks * 16);
                    mma16816(S_[2 * jj],     a0, a1, a2, a3, b0, b1);
                    mma16816(S_[2 * jj + 1], a0, a1, a2, a3, b2, b3);
                }
            }

            // ---- causal mask ----
            if (k0 + 63 > qw) {
                const int r0 = qw + g, r1 = r0 + 8;
#pragma unroll
                for (int j = 0; j < 8; j++) {
                    int c0 = k0 + j * 8 + 2 * q4;
                    if (c0     > r0) S_[j][0] = -INFINITY;
                    if (c0 + 1 > r0) S_[j][1] = -INFINITY;
                    if (c0     > r1) S_[j][2] = -INFINITY;
                    if (c0 + 1 > r1) S_[j][3] = -INFINITY;
                }
            }

            // ---- online softmax (exp2 domain) ----
            float rmax0 = -INFINITY, rmax1 = -INFINITY;
#pragma unroll
            for (int j = 0; j < 8; j++) {
                rmax0 = fmaxf(rmax0, fmaxf(S_[j][0], S_[j][1]));
                rmax1 = fmaxf(rmax1, fmaxf(S_[j][2], S_[j][3]));
            }
            rmax0 = fmaxf(rmax0, __shfl_xor_sync(0xffffffffu, rmax0, 1));
            rmax0 = fmaxf(rmax0, __shfl_xor_sync(0xffffffffu, rmax0, 2));
            rmax1 = fmaxf(rmax1, __shfl_xor_sync(0xffffffffu, rmax1, 1));
            rmax1 = fmaxf(rmax1, __shfl_xor_sync(0xffffffffu, rmax1, 2));

            float nm0 = fmaxf(m0, rmax0), nm1 = fmaxf(m1, rmax1);
            float corr0 = ex2f(m0 - nm0), corr1 = ex2f(m1 - nm1);
            m0 = nm0; m1 = nm1;

            // p in fp32; split into hi (ph) + lo (pl) bf16 pairs
            uint32_t ph[8][2], pl[8][2];
            float sum0 = 0.f, sum1 = 0.f;
#pragma unroll
            for (int j = 0; j < 8; j++) {
                float p00 = ex2f(S_[j][0] - nm0);
                float p01 = ex2f(S_[j][1] - nm0);
                float p10 = ex2f(S_[j][2] - nm1);
                float p11 = ex2f(S_[j][3] - nm1);
                sum0 += p00 + p01;
                sum1 += p10 + p11;
                __nv_bfloat16 h00, l00, h01, l01, h10, l10, h11, l11;
                split_bf16(p00, h00, l00); split_bf16(p01, h01, l01);
                split_bf16(p10, h10, l10); split_bf16(p11, h11, l11);
                __nv_bfloat162 t0; t0.x = h00; t0.y = h01;
                __nv_bfloat162 t1; t1.x = h10; t1.y = h11;
                __nv_bfloat162 t2; t2.x = l00; t2.y = l01;
                __nv_bfloat162 t3; t3.x = l10; t3.y = l11;
                ph[j][0] = *(uint32_t*)&t0; ph[j][1] = *(uint32_t*)&t1;
                pl[j][0] = *(uint32_t*)&t2; pl[j][1] = *(uint32_t*)&t3;
            }
            sum0 += __shfl_xor_sync(0xffffffffu, sum0, 1);
            sum0 += __shfl_xor_sync(0xffffffffu, sum0, 2);
            sum1 += __shfl_xor_sync(0xffffffffu, sum1, 1);
            sum1 += __shfl_xor_sync(0xffffffffu, sum1, 2);
            l0 = l0 * corr0 + sum0;
            l1 = l1 * corr1 + sum1;

#pragma unroll
            for (int j = 0; j < 8; j++) {
                O[j][0] *= corr0; O[j][1] *= corr0;
                O[j][2] *= corr1; O[j][3] *= corr1;
            }

            // ---- PV: vh with (ph + pl) [fragment reuse], then vl with ph ----
#pragma unroll
            for (int ksp = 0; ksp < 4; ksp++) {
                uint32_t h0 = ph[2 * ksp][0],     h1 = ph[2 * ksp][1];
                uint32_t h2 = ph[2 * ksp + 1][0], h3 = ph[2 * ksp + 1][1];
                uint32_t lo0 = pl[2 * ksp][0],     lo1 = pl[2 * ksp][1];
                uint32_t lo2 = pl[2 * ksp + 1][0], lo3 = pl[2 * ksp + 1][1];
#pragma unroll
                for (int jj = 0; jj < 4; jj++) {
                    uint32_t b0, b1, b2, b3;
                    ldsm4(b0, b1, b2, b3, Vs + vOffE + jj * 16 * VLD + ksp * 16);
                    mma16816(O[2 * jj],     h0, h1, h2, h3, b0, b1);
                    mma16816(O[2 * jj + 1], h0, h1, h2, h3, b2, b3);
                    mma16816(O[2 * jj],     lo0, lo1, lo2, lo3, b0, b1);
                    mma16816(O[2 * jj + 1], lo0, lo1, lo2, lo3, b2, b3);
                }
            }
#pragma unroll
            for (int ksp = 0; ksp < 4; ksp++) {
                uint32_t h0 = ph[2 * ksp][0],     h1 = ph[2 * ksp][1];
                uint32_t h2 = ph[2 * ksp + 1][0], h3 = ph[2 * ksp + 1][1];
#pragma unroll
                for (int jj = 0; jj < 4; jj++) {
                    uint32_t b0, b1, b2, b3;
                    ldsm4(b0, b1, b2, b3, Vs + vOffE + jj * 16 * VLD + 64 + ksp * 16);
                    mma16816(O[2 * jj],     h0, h1, h2, h3, b0, b1);
                    mma16816(O[2 * jj + 1], h0, h1, h2, h3, b2, b3);
                }
            }
        }

        __syncthreads();
        if (t + 2 < nt) issueTile(t + 2, t & 1);
    }

    // ---- epilogue: write [h|h|l] bf16 split of ctx directly ----
    const float inv0 = 1.f / l0, inv1 = 1.f / l1;
    const int r0 = b * SEQ + qw + g;
    const int colBase = h * HEAD_DIM + 2 * q4;
#pragma unroll
    for (int jn = 0; jn < 8; jn++) {
        int col = colBase + jn * 8;
        float v00 = O[jn][0] * inv0, v01 = O[jn][1] * inv0;
        float v10 = O[jn][2] * inv1, v11 = O[jn][3] * inv1;
        __nv_bfloat16 h00, l00, h01, l01, h10, l10, h11, l11;
        split_bf16(v00, h00, l00); split_bf16(v01, h01, l01);
        split_bf16(v10, h10, l10); split_bf16(v11, h11, l11);
        __nv_bfloat162 hh0; hh0.x = h00; hh0.y = h01;
        __nv_bfloat162 ll0; ll0.x = l00; ll0.y = l01;
        __nv_bfloat162 hh1; hh1.x = h10; hh1.y = h11;
        __nv_bfloat162 ll1; ll1.x = l10; ll1.y = l11;
        size_t base0 = (size_t)r0 * KP + col;
        size_t base1 = base0 + (size_t)8 * KP;
        *(uint32_t*)&ctx2[base0]             = *(uint32_t*)&hh0;
        *(uint32_t*)&ctx2[base0 + D_MODEL]   = *(uint32_t*)&hh0;
        *(uint32_t*)&ctx2[base0 + 2*D_MODEL] = *(uint32_t*)&ll0;
        *(uint32_t*)&ctx2[base1]             = *(uint32_t*)&hh1;
        *(uint32_t*)&ctx2[base1 + D_MODEL]   = *(uint32_t*)&hh1;
        *(uint32_t*)&ctx2[base1 + 2*D_MODEL] = *(uint32_t*)&ll1;
    }
}

// ============================================================================
// Launch
// ============================================================================
extern "C" void kernel_launch(void* const* d_in, const int* in_sizes, int n_in,
                              void* d_out, int out_size)
{
    const float* x  = (const float*)d_in[0];
    const float* Wq = (const float*)d_in[1];
    const float* Wk = (const float*)d_in[2];
    const float* Wv = (const float*)d_in[3];
    const float* Wo = (const float*)d_in[4];
    float* out = (float*)d_out;

    float *q, *k, *v;
    __nv_bfloat16 *x2, *ctx2, *wq2, *wk2, *wv2, *wo2, *Q2, *K2, *Vt2;
    cudaGetSymbolAddress((void**)&q,    g_q);
    cudaGetSymbolAddress((void**)&k,    g_k);
    cudaGetSymbolAddress((void**)&v,    g_v);
    cudaGetSymbolAddress((void**)&x2,   g_x2);
    cudaGetSymbolAddress((void**)&ctx2, g_ctx2);
    cudaGetSymbolAddress((void**)&wq2,  g_wq2);
    cudaGetSymbolAddress((void**)&wk2,  g_wk2);
    cudaGetSymbolAddress((void**)&wv2,  g_wv2);
    cudaGetSymbolAddress((void**)&wo2,  g_wo2);
    cudaGetSymbolAddress((void**)&Q2,   g_Q2);
    cudaGetSymbolAddress((void**)&K2,   g_K2);
    cudaGetSymbolAddress((void**)&Vt2,  g_Vt2);

    // 1. split/convert inputs + weights
    split_rows_kernel<<<(M_ROWS * 512 + 255) / 256, 256>>>(x, x2, M_ROWS);
    dim3 wtGrid(32, 32), wtBlock(32, 8);
    split_wT_kernel<<<wtGrid, wtBlock>>>(Wq, wq2);
    split_wT_kernel<<<wtGrid, wtBlock>>>(Wk, wk2);
    split_wT_kernel<<<wtGrid, wtBlock>>>(Wv, wv2);
    split_wT_kernel<<<wtGrid, wtBlock>>>(Wo, wo2);

    // 2. Q/K/V projections
    dim3 gemmGrid(D_MODEL / 128, M_ROWS / 128);
    gemm_bf16_kernel<<<gemmGrid, 256>>>(x2, wq2, q, D_MODEL);
    gemm_bf16_kernel<<<gemmGrid, 256>>>(x2, wk2, k, D_MODEL);
    gemm_bf16_kernel<<<gemmGrid, 256>>>(x2, wv2, v, D_MODEL);

    // 3. attention operand prep
    qk2_split_kernel<<<(M_ROWS * 512 + 255) / 256, 256>>>(q, k, Q2, K2);
    vt2_split_kernel<<<dim3(SEQ / 64, 32), 256>>>(v, Vt2);

    // 4. tensor-core flash attention (writes ctx2 split directly)
    cudaFuncSetAttribute(attn_tc_kernel, cudaFuncAttributeMaxDynamicSharedMemorySize,
                         ATT_SMEM);
    attn_tc_kernel<<<dim3(SEQ / 128, 32), 256, ATT_SMEM>>>(Q2, K2, Vt2, ctx2);

    // 5. output projection
    gemm_bf16_kernel<<<gemmGrid, 256>>>(ctx2, wo2, out, D_MODEL);
}